// round 1
// baseline (speedup 1.0000x reference)
#include <cuda_runtime.h>
#include <math.h>

// CapsuleLayer dynamic routing, fused: never materialize u_hat (302MB).
// Recompute t[b,c,o] = sum_i W[n,c,o,i]*x[b,n,i] per pass; W (37.7MB) stays L2-hot.
//
// Passes per kernel_launch:
//   k_sj (s-pass, c weighted)  -> partials g_spart[chunk][b][co]
//   k_squash (reduce+squash)   -> g_v or d_out
//   k_bupd (agreement)         -> g_bupd[bg][n][c]
//   k_softmax (b update + softmax over n per c) -> g_b, g_cij

#define BB 64
#define NN 2304
#define CC 32
#define OO 16
#define II 8
#define CO 512        // C*O
#define WROW 4096     // C*O*I floats per n
#define NCHUNK 144
#define NPC 16        // NN / NCHUNK
#define BG 32         // batch rows per block
#define NBG 2         // BB / BG

// scratch (device globals: no runtime allocation allowed)
__device__ float g_spart[(size_t)NCHUNK * BB * CO];  // 18.9 MB partials
__device__ float g_v[BB * CO];                       // v[b][co]
__device__ float g_bupd[NBG * NN * CC];              // per-bgroup agreement partials
__device__ float g_b[NN * CC];                       // routing logits
__device__ float g_cij[NN * CC];                     // softmax(b) over n

// ---------------------------------------------------------------------------
// s-pass: each block = (n-chunk, b-group). 256 threads; thread owns co pair
// (2t, 2t+1) x 32 batch rows -> 64 register accumulators.
// ---------------------------------------------------------------------------
__global__ __launch_bounds__(256, 2)
void k_sj(const float* __restrict__ x, const float* __restrict__ W, int use_cij)
{
    const int chunk = blockIdx.x;
    const int bg    = blockIdx.y;
    const int t     = threadIdx.x;
    const int n0    = chunk * NPC;
    const int co0   = 2 * t;
    const int cidx  = t >> 3;          // c of both co's

    __shared__ float4 xs4[NPC * BG * 2];   // x tile: [nn][b][i4], 16KB
    __shared__ float  cs[NPC * CC];        // c_ij rows for this chunk

    // load x tile
    const float4* x4 = (const float4*)x;
    for (int idx = t; idx < NPC * BG * 2; idx += 256) {
        int nn  = idx >> 6;
        int rem = idx & 63;
        int b   = rem >> 1;
        int i4  = rem & 1;
        xs4[idx] = x4[((size_t)(bg * BG + b) * NN + (n0 + nn)) * 2 + i4];
    }
    if (use_cij) {
        for (int idx = t; idx < NPC * CC; idx += 256)
            cs[idx] = g_cij[(size_t)n0 * CC + idx];
    }
    __syncthreads();

    float acc0[BG], acc1[BG];
#pragma unroll
    for (int b = 0; b < BG; b++) { acc0[b] = 0.0f; acc1[b] = 0.0f; }

    const float4* wbase = (const float4*)(W + (size_t)n0 * WROW + (size_t)co0 * II);

    for (int nn = 0; nn < NPC; nn++) {
        float cw = use_cij ? cs[nn * CC + cidx] : (1.0f / (float)NN);
        const float4* wp = wbase + (size_t)nn * (WROW / 4);
        float4 wa0 = wp[0], wb0 = wp[1], wa1 = wp[2], wb1 = wp[3];
        float wc0[8] = {wa0.x*cw, wa0.y*cw, wa0.z*cw, wa0.w*cw,
                        wb0.x*cw, wb0.y*cw, wb0.z*cw, wb0.w*cw};
        float wc1[8] = {wa1.x*cw, wa1.y*cw, wa1.z*cw, wa1.w*cw,
                        wb1.x*cw, wb1.y*cw, wb1.z*cw, wb1.w*cw};
        const float4* xr = xs4 + nn * (BG * 2);
#pragma unroll 8
        for (int b = 0; b < BG; b++) {
            float4 xa = xr[2 * b];
            float4 xb = xr[2 * b + 1];
            float s0 = acc0[b], s1 = acc1[b];
            s0 = fmaf(wc0[0], xa.x, s0); s0 = fmaf(wc0[1], xa.y, s0);
            s0 = fmaf(wc0[2], xa.z, s0); s0 = fmaf(wc0[3], xa.w, s0);
            s0 = fmaf(wc0[4], xb.x, s0); s0 = fmaf(wc0[5], xb.y, s0);
            s0 = fmaf(wc0[6], xb.z, s0); s0 = fmaf(wc0[7], xb.w, s0);
            s1 = fmaf(wc1[0], xa.x, s1); s1 = fmaf(wc1[1], xa.y, s1);
            s1 = fmaf(wc1[2], xa.z, s1); s1 = fmaf(wc1[3], xa.w, s1);
            s1 = fmaf(wc1[4], xb.x, s1); s1 = fmaf(wc1[5], xb.y, s1);
            s1 = fmaf(wc1[6], xb.z, s1); s1 = fmaf(wc1[7], xb.w, s1);
            acc0[b] = s0; acc1[b] = s1;
        }
    }

    float* spbase = g_spart + ((size_t)chunk * BB + (size_t)bg * BG) * CO + co0;
#pragma unroll
    for (int b = 0; b < BG; b++) {
        *(float2*)(spbase + (size_t)b * CO) = make_float2(acc0[b], acc1[b]);
    }
}

// ---------------------------------------------------------------------------
// reduce partials + squash. id = b*512 + co. final -> write d_out, else g_v.
// ---------------------------------------------------------------------------
__global__ void k_squash(float* __restrict__ dout, int final_pass)
{
    int id = blockIdx.x * 256 + threadIdx.x;   // 0..32767
    float s = 0.0f;
#pragma unroll 4
    for (int ch = 0; ch < NCHUNK; ch++)
        s += g_spart[(size_t)ch * (BB * CO) + id];
    // squash elementwise: s^3/((1+s^2)|s|) == s*|s|/(1+s^2)
    float vv = s * fabsf(s) / (1.0f + s * s);
    if (final_pass) dout[id] = vv;
    else            g_v[id]  = vv;
}

// ---------------------------------------------------------------------------
// agreement pass: per (n, b-group) compute sum_{b,o} t[b,c,o]*v[b,c,o].
// Thread owns co pair (2t,2t+1) -> both same c; 8 consecutive threads cover
// all 16 o of one c -> shfl reduce width 8.
// ---------------------------------------------------------------------------
__global__ __launch_bounds__(256, 2)
void k_bupd(const float* __restrict__ x, const float* __restrict__ W)
{
    const int chunk = blockIdx.x;
    const int bg    = blockIdx.y;
    const int t     = threadIdx.x;
    const int n0    = chunk * NPC;
    const int co0   = 2 * t;
    const int cidx  = t >> 3;

    __shared__ float4 xs4[NPC * BG * 2];

    const float4* x4 = (const float4*)x;
    for (int idx = t; idx < NPC * BG * 2; idx += 256) {
        int nn  = idx >> 6;
        int rem = idx & 63;
        int b   = rem >> 1;
        int i4  = rem & 1;
        xs4[idx] = x4[((size_t)(bg * BG + b) * NN + (n0 + nn)) * 2 + i4];
    }
    __syncthreads();

    // v for this thread's co pair, all 32 b rows (register-resident)
    float v0[BG], v1[BG];
#pragma unroll
    for (int b = 0; b < BG; b++) {
        float2 vv = *(const float2*)(g_v + (size_t)(bg * BG + b) * CO + co0);
        v0[b] = vv.x; v1[b] = vv.y;
    }

    const float4* wbase = (const float4*)(W + (size_t)n0 * WROW + (size_t)co0 * II);

    for (int nn = 0; nn < NPC; nn++) {
        const float4* wp = wbase + (size_t)nn * (WROW / 4);
        float4 wa0 = wp[0], wb0 = wp[1], wa1 = wp[2], wb1 = wp[3];
        float w0[8] = {wa0.x, wa0.y, wa0.z, wa0.w, wb0.x, wb0.y, wb0.z, wb0.w};
        float w1[8] = {wa1.x, wa1.y, wa1.z, wa1.w, wb1.x, wb1.y, wb1.z, wb1.w};
        const float4* xr = xs4 + nn * (BG * 2);
        float p0 = 0.0f, p1 = 0.0f;
#pragma unroll 8
        for (int b = 0; b < BG; b++) {
            float4 xa = xr[2 * b];
            float4 xb = xr[2 * b + 1];
            float t0 = w0[0] * xa.x;
            t0 = fmaf(w0[1], xa.y, t0); t0 = fmaf(w0[2], xa.z, t0);
            t0 = fmaf(w0[3], xa.w, t0); t0 = fmaf(w0[4], xb.x, t0);
            t0 = fmaf(w0[5], xb.y, t0); t0 = fmaf(w0[6], xb.z, t0);
            t0 = fmaf(w0[7], xb.w, t0);
            float t1 = w1[0] * xa.x;
            t1 = fmaf(w1[1], xa.y, t1); t1 = fmaf(w1[2], xa.z, t1);
            t1 = fmaf(w1[3], xa.w, t1); t1 = fmaf(w1[4], xb.x, t1);
            t1 = fmaf(w1[5], xb.y, t1); t1 = fmaf(w1[6], xb.z, t1);
            t1 = fmaf(w1[7], xb.w, t1);
            p0 = fmaf(t0, v0[b], p0);
            p1 = fmaf(t1, v1[b], p1);
        }
        float p = p0 + p1;
        // reduce over the 8 threads (16 o's) of this c
        p += __shfl_down_sync(0xffffffffu, p, 4, 8);
        p += __shfl_down_sync(0xffffffffu, p, 2, 8);
        p += __shfl_down_sync(0xffffffffu, p, 1, 8);
        if ((t & 7) == 0)
            g_bupd[(size_t)bg * NN * CC + (size_t)(n0 + nn) * CC + cidx] = p;
    }
}

// ---------------------------------------------------------------------------
// combine agreement partials into b, then softmax over n per c.
// One block per c (32 blocks), 256 threads.
// ---------------------------------------------------------------------------
__global__ void k_softmax(int iter0)
{
    const int c = blockIdx.x;
    const int t = threadIdx.x;
    __shared__ float bs[NN];      // 9.2 KB
    __shared__ float red[256];

    for (int n = t; n < NN; n += 256) {
        float bold = iter0 ? 0.0f : g_b[(size_t)n * CC + c];
        float bu = (g_bupd[(size_t)n * CC + c] +
                    g_bupd[(size_t)NN * CC + (size_t)n * CC + c]) * (1.0f / (float)BB);
        float bn = bold + bu;
        g_b[(size_t)n * CC + c] = bn;
        bs[n] = bn;
    }
    __syncthreads();

    float m = -3.0e38f;
    for (int n = t; n < NN; n += 256) m = fmaxf(m, bs[n]);
    red[t] = m;
    __syncthreads();
    for (int off = 128; off > 0; off >>= 1) {
        if (t < off) red[t] = fmaxf(red[t], red[t + off]);
        __syncthreads();
    }
    m = red[0];
    __syncthreads();

    float sum = 0.0f;
    for (int n = t; n < NN; n += 256) {
        float e = expf(bs[n] - m);
        bs[n] = e;
        sum += e;
    }
    red[t] = sum;
    __syncthreads();
    for (int off = 128; off > 0; off >>= 1) {
        if (t < off) red[t] = red[t] + red[t + off];
        __syncthreads();
    }
    float inv = 1.0f / red[0];
    __syncthreads();

    for (int n = t; n < NN; n += 256)
        g_cij[(size_t)n * CC + c] = bs[n] * inv;
}

// ---------------------------------------------------------------------------
extern "C" void kernel_launch(void* const* d_in, const int* in_sizes, int n_in,
                              void* d_out, int out_size)
{
    const float* x = (const float*)d_in[0];   // [B, N, I] fp32
    const float* W = (const float*)d_in[1];   // [N, C, O, I] fp32
    float* out = (float*)d_out;               // [B, C, O, 1] fp32

    dim3 g(NCHUNK, NBG);

    // iteration 0 (uniform c = 1/N)
    k_sj<<<g, 256>>>(x, W, 0);
    k_squash<<<128, 256>>>(out, 0);
    k_bupd<<<g, 256>>>(x, W);
    k_softmax<<<CC, 256>>>(1);

    // iteration 1
    k_sj<<<g, 256>>>(x, W, 1);
    k_squash<<<128, 256>>>(out, 0);
    k_bupd<<<g, 256>>>(x, W);
    k_softmax<<<CC, 256>>>(0);

    // iteration 2 (final: only s + squash, write output)
    k_sj<<<g, 256>>>(x, W, 1);
    k_squash<<<128, 256>>>(out, 1);
}